// round 3
// baseline (speedup 1.0000x reference)
#include <cuda_runtime.h>
#include <math.h>
#include <stdint.h>

#define S_LEN 16384
#define I_DIM 64
#define R_DIM 2048
#define H_DIM 128
#define O_DIM 50
#define NBLK  128
#define ROWS_PER_BLK 16   // 128*16 = 2048
#define NTHR  512

// ---------------- device scratch (static; no allocations) ----------------
__device__ float g_h[2][R_DIM];
__device__ float g_states[(size_t)S_LEN * R_DIM];   // 134 MB
__device__ float g_Wc[O_DIM * R_DIM];               // folded fc2@fc1
__device__ float g_bc[O_DIM];                       // folded bias
__device__ unsigned g_count = 0;                    // monotone across replays
__device__ unsigned g_gen   = 0;                    // monotone across replays

// packed f32x2 FMA: d = a*b + d   (sm_100+; ptxas won't emit FFMA2 from C++)
__device__ __forceinline__ void ffma2(uint64_t& d, uint64_t a, uint64_t b) {
    asm("fma.rn.f32x2 %0, %1, %2, %0;" : "+l"(d) : "l"(a), "l"(b));
}

// Grid-wide barrier for exactly NBLK co-resident blocks.
// Monotone counters -> safe across CUDA-graph replays (2^32 % NBLK == 0).
__device__ __forceinline__ void grid_barrier() {
    __syncthreads();
    if (threadIdx.x == 0) {
        unsigned gsnap = *(volatile unsigned*)&g_gen;  // gen can't advance until WE arrive
        __threadfence();                                // release our stores
        unsigned old = atomicAdd(&g_count, 1u);
        if ((old & (NBLK - 1u)) == (NBLK - 1u)) {
            __threadfence();
            atomicAdd(&g_gen, 1u);
        } else {
            while (*(volatile unsigned*)&g_gen == gsnap) { }
        }
        __threadfence();                                // acquire others' stores
    }
    __syncthreads();
}

// ---------------- persistent recurrence kernel ----------------
// W lives in registers: block b owns rows [16b,16b+16); thread (grp,tg) owns
// rows 16b+4*grp..+3, packed f32x2 column chunks.
__global__ void __launch_bounds__(NTHR, 1) esn_kernel(
    const float* __restrict__ x,     // [S,64]
    const float* __restrict__ Win,   // [2048,64]
    const float* __restrict__ W)     // [2048,2048]
{
    __shared__ float4 hs4[R_DIM / 4];                    // staged h (8 KB)
    __shared__ float  win_s[ROWS_PER_BLK][I_DIM];        // 4 KB
    __shared__ float  xs[I_DIM];                         // 256 B
    __shared__ float  psum2[ROWS_PER_BLK][4];

    const int tid  = threadIdx.x;
    const int lane = tid & 31;
    const int wrp  = tid >> 5;          // 0..15
    const int grp  = tid >> 7;          // 0..3
    const int tg   = tid & 127;         // 0..127
    const int wig  = (tid >> 5) & 3;    // warp-in-group
    const int rbase = blockIdx.x * ROWS_PER_BLK;

    // Load W slice into registers as packed f32x2 (64 floats/thread; 16 MB chip-wide, once).
    uint64_t w2[4][8];
#pragma unroll
    for (int r = 0; r < 4; r++) {
        const ulonglong2* Wrow = (const ulonglong2*)(W + (size_t)(rbase + grp * 4 + r) * R_DIM);
#pragma unroll
        for (int j = 0; j < 4; j++) {
            ulonglong2 v = Wrow[tg + 128 * j];   // 16B = 4 floats = 2 packed pairs
            w2[r][2 * j]     = v.x;
            w2[r][2 * j + 1] = v.y;
        }
    }
    // Win slice -> SMEM (16 rows x 64)
    if (tid < 256) {
        int rr = tid >> 4, c4 = tid & 15;
        ((float4*)&win_s[rr][0])[c4] = ((const float4*)(Win + (size_t)(rbase + rr) * I_DIM))[c4];
    }
    // zero h0 (this block's rows), every launch
    if (tid < ROWS_PER_BLK) g_h[0][rbase + tid] = 0.0f;
    grid_barrier();

    for (int t = 0; t < S_LEN; t++) {
        const int p = t & 1;
        // stage full h + x_t into SMEM
        hs4[tid] = ((const float4*)g_h[p])[tid];
        if (tid < I_DIM / 4) ((float4*)xs)[tid] = ((const float4*)(x + (size_t)t * I_DIM))[tid];
        __syncthreads();

        uint64_t h2[8];
        {
            const ulonglong2* hp = (const ulonglong2*)hs4;
#pragma unroll
            for (int j = 0; j < 4; j++) {
                ulonglong2 v = hp[tg + 128 * j];
                h2[2 * j]     = v.x;
                h2[2 * j + 1] = v.y;
            }
        }

        float acc[4];
#pragma unroll
        for (int r = 0; r < 4; r++) {
            uint64_t a2 = 0ull;   // packed (0.0f, 0.0f)
#pragma unroll
            for (int j = 0; j < 8; j++) ffma2(a2, w2[r][j], h2[j]);
            float2 f = *(float2*)&a2;
            acc[r] = f.x + f.y;
        }
        // warp-reduce the 4 row partials; one partial per (row, warp-in-group)
#pragma unroll
        for (int r = 0; r < 4; r++) {
            float a = acc[r];
#pragma unroll
            for (int s = 16; s > 0; s >>= 1) a += __shfl_xor_sync(0xffffffffu, a, s);
            if (lane == 0) psum2[grp * 4 + r][wig] = a;
        }
        __syncthreads();

        // stage 2: warp wrp finalizes row wrp (adds xin on the fly)
        {
            const int row = wrp;
            const float* winr = win_s[row];
            float v = winr[2 * lane] * xs[2 * lane] + winr[2 * lane + 1] * xs[2 * lane + 1];
            if (lane < 4) v += psum2[row][lane];
#pragma unroll
            for (int s = 16; s > 0; s >>= 1) v += __shfl_xor_sync(0xffffffffu, v, s);
            if (lane == 0) {
                const int rg = rbase + row;
                float hold = ((const float*)hs4)[rg];
                float hn = 0.5f * hold + 0.5f * tanhf(v);
                g_h[p ^ 1][rg] = hn;
                g_states[(size_t)t * R_DIM + rg] = hn;
            }
        }
        grid_barrier();
    }
}

// ---------------- fold fc2@fc1 into Wc (50x2048) and bc (50) ----------------
__global__ void wc_kernel(const float* __restrict__ fc1_w,  // [128,2048]
                          const float* __restrict__ fc1_b,  // [128]
                          const float* __restrict__ fc2_w,  // [50,128]
                          const float* __restrict__ fc2_b)  // [50]
{
    const int r = blockIdx.x * 256 + threadIdx.x;  // 0..2047
    const int o = blockIdx.y;                      // 0..49
    float a = 0.0f;
    for (int h = 0; h < H_DIM; h++)
        a += fc2_w[o * H_DIM + h] * fc1_w[(size_t)h * R_DIM + r];
    g_Wc[o * R_DIM + r] = a;
    if (blockIdx.x == 0 && threadIdx.x == 0) {
        float b = fc2_b[o];
        for (int h = 0; h < H_DIM; h++) b += fc2_w[o * H_DIM + h] * fc1_b[h];
        g_bc[o] = b;
    }
}

// ---------------- out = states @ Wc^T + bc ----------------
#define GT 64
#define KT 64
__global__ void __launch_bounds__(256) out_kernel(float* __restrict__ out) {
    __shared__ float s_s[GT][KT + 1];    // pad to kill 32-way conflicts
    __shared__ float wc_s[O_DIM][KT];    // broadcast reads, no pad needed

    const int tid = threadIdx.x;
    const int t0 = blockIdx.x * GT;
    const int r  = tid & 63;             // row within tile
    const int oq = tid >> 6;             // 0..3
    const int OB = 13;                   // ceil(50/4)
    const int o0 = oq * OB;

    float acc[OB];
#pragma unroll
    for (int i = 0; i < OB; i++) acc[i] = 0.0f;

    for (int k0 = 0; k0 < R_DIM; k0 += KT) {
        // load S tile 64x64 (float4 from gmem, scalar STS due to pad)
#pragma unroll
        for (int i = 0; i < 4; i++) {
            int idx = tid + 256 * i;          // float4 index 0..1023
            int rr = idx >> 4, c4 = idx & 15;
            float4 v = ((const float4*)(g_states + (size_t)(t0 + rr) * R_DIM + k0))[c4];
            s_s[rr][4 * c4 + 0] = v.x;
            s_s[rr][4 * c4 + 1] = v.y;
            s_s[rr][4 * c4 + 2] = v.z;
            s_s[rr][4 * c4 + 3] = v.w;
        }
        // load Wc tile 50x64
        for (int idx = tid; idx < O_DIM * (KT / 4); idx += 256) {
            int rr = idx >> 4, c4 = idx & 15;
            ((float4*)&wc_s[rr][0])[c4] = ((const float4*)(g_Wc + (size_t)rr * R_DIM + k0))[c4];
        }
        __syncthreads();
#pragma unroll 8
        for (int kk = 0; kk < KT; kk++) {
            float sv = s_s[r][kk];
#pragma unroll
            for (int i = 0; i < OB; i++) {
                int o = o0 + i;
                if (o < O_DIM) acc[i] += sv * wc_s[o][kk];
            }
        }
        __syncthreads();
    }
#pragma unroll
    for (int i = 0; i < OB; i++) {
        int o = o0 + i;
        if (o < O_DIM) out[(size_t)(t0 + r) * O_DIM + o] = acc[i] + g_bc[o];
    }
}

// ---------------- launcher ----------------
extern "C" void kernel_launch(void* const* d_in, const int* in_sizes, int n_in,
                              void* d_out, int out_size) {
    (void)in_sizes; (void)n_in; (void)out_size;
    const float* x     = (const float*)d_in[0];
    const float* Win   = (const float*)d_in[1];
    const float* W     = (const float*)d_in[2];
    const float* fc1_w = (const float*)d_in[3];
    const float* fc1_b = (const float*)d_in[4];
    const float* fc2_w = (const float*)d_in[5];
    const float* fc2_b = (const float*)d_in[6];
    float* out = (float*)d_out;

    wc_kernel<<<dim3(R_DIM / 256, O_DIM), 256>>>(fc1_w, fc1_b, fc2_w, fc2_b);
    esn_kernel<<<NBLK, NTHR>>>(x, Win, W);
    out_kernel<<<S_LEN / GT, 256>>>(out);
}